// round 13
// baseline (speedup 1.0000x reference)
#include <cuda_runtime.h>
#include <cuda_fp16.h>
#include <stdint.h>
#include <math.h>

#define NMAX 50000
#define EMAX 800000
#define BMAX 128

// ---------------- scratch ----------------
__device__ __half2 d_XHh [NMAX * 64];    // GEMM output fp16
__device__ __half2 d_H1h [NMAX * 64];    // layer-1 output fp16
__device__ __half  d_Wt1 [128 * 128];    // W1^T fp16 [n][k]
__device__ __half  d_Wt2 [128 * 128];    // W2^T fp16 [n][k]
__device__ float   d_ASRC[NMAX * 4];
__device__ float   d_ADST[NMAX * 4];
__device__ int     d_deg   [NMAX];
__device__ int     d_rowptr[NMAX + 1];
__device__ int     d_cursor[NMAX];
__device__ int     d_col   [EMAX + NMAX];
__device__ float   d_gsum  [BMAX * 32];
__device__ int     d_bsum  [64];

// ---------------- init + weight prep ----------------
__global__ void k_init(const float* __restrict__ W1, const float* __restrict__ W2,
                       int N, int B) {
    int i0 = blockIdx.x * blockDim.x + threadIdx.x;
    int stride = gridDim.x * blockDim.x;
    for (int t = i0; t < N; t += stride) d_deg[t] = 1;   // self loop pre-counted
    for (int t = i0; t < B * 32; t += stride) d_gsum[t] = 0.f;
    for (int t = i0; t < 16384; t += stride) {
        int n = t >> 7, k = t & 127;
        d_Wt1[n * 128 + k] = __float2half_rn(W1[k * 128 + n]);
        d_Wt2[n * 128 + k] = __float2half_rn(W2[k * 128 + n]);
    }
}

// ---------------- tensor-core GEMM + fused attention dots ----------------
template <bool HIN>
__global__ void __launch_bounds__(256, 2) k_gemm_att(
    const void* __restrict__ Xv, const __half* __restrict__ Wt,
    const float* __restrict__ att_s, const float* __restrict__ att_d,
    int nrows)
{
    __shared__ __half Xs[128][40];
    __shared__ __half Ws[128][40];

    int tid = threadIdx.x;
    int wid = tid >> 5, lane = tid & 31;
    int g = lane >> 2, t = lane & 3;
    int wr = wid >> 1, wc = wid & 1;
    int rowBase = blockIdx.x * 128;

    float acc[2][8][4];
#pragma unroll
    for (int mi = 0; mi < 2; mi++)
#pragma unroll
        for (int ni = 0; ni < 8; ni++)
#pragma unroll
            for (int q = 0; q < 4; q++) acc[mi][ni][q] = 0.f;

    for (int k0 = 0; k0 < 128; k0 += 32) {
        if (HIN) {
            const uint4* Xh = (const uint4*)Xv;
#pragma unroll
            for (int it = 0; it < 2; it++) {
                int idx = tid + 256 * it;
                int r = idx >> 2;
                int c8 = (idx & 3) * 8;
                int gr = rowBase + r;
                uint4 v = (gr < nrows) ? Xh[gr * 16 + (k0 >> 3) + (c8 >> 3)]
                                       : make_uint4(0u, 0u, 0u, 0u);
                *(uint4*)&Xs[r][c8] = v;
            }
        } else {
            const float* X = (const float*)Xv;
#pragma unroll
            for (int it = 0; it < 4; it++) {
                int idx = tid + 256 * it;
                int r = idx >> 3;
                int c4 = (idx & 7) * 4;
                int gr = rowBase + r;
                float4 v = (gr < nrows) ? *(const float4*)&X[gr * 128 + k0 + c4]
                                        : make_float4(0.f, 0.f, 0.f, 0.f);
                __half2 h0 = __floats2half2_rn(v.x, v.y);
                __half2 h1 = __floats2half2_rn(v.z, v.w);
                uint2 p; p.x = *(uint32_t*)&h0; p.y = *(uint32_t*)&h1;
                *(uint2*)&Xs[r][c4] = p;
            }
        }
#pragma unroll
        for (int it = 0; it < 2; it++) {
            int idx = tid + 256 * it;
            int n = idx >> 2;
            int c8 = (idx & 3) * 8;
            *(uint4*)&Ws[n][c8] = *(const uint4*)&Wt[n * 128 + k0 + c8];
        }
        __syncthreads();
#pragma unroll
        for (int ks = 0; ks < 2; ks++) {
            int kb = ks * 16;
            uint32_t a[2][4];
#pragma unroll
            for (int mi = 0; mi < 2; mi++) {
                int ar = wr * 32 + mi * 16 + g;
                a[mi][0] = *(const uint32_t*)&Xs[ar][kb + 2 * t];
                a[mi][1] = *(const uint32_t*)&Xs[ar + 8][kb + 2 * t];
                a[mi][2] = *(const uint32_t*)&Xs[ar][kb + 2 * t + 8];
                a[mi][3] = *(const uint32_t*)&Xs[ar + 8][kb + 2 * t + 8];
            }
#pragma unroll
            for (int ni = 0; ni < 8; ni++) {
                int bn = wc * 64 + ni * 8 + g;
                uint32_t b0 = *(const uint32_t*)&Ws[bn][kb + 2 * t];
                uint32_t b1 = *(const uint32_t*)&Ws[bn][kb + 2 * t + 8];
#pragma unroll
                for (int mi = 0; mi < 2; mi++) {
                    asm volatile(
                        "mma.sync.aligned.m16n8k16.row.col.f32.f16.f16.f32 "
                        "{%0,%1,%2,%3}, {%4,%5,%6,%7}, {%8,%9}, {%0,%1,%2,%3};"
                        : "+f"(acc[mi][ni][0]), "+f"(acc[mi][ni][1]),
                          "+f"(acc[mi][ni][2]), "+f"(acc[mi][ni][3])
                        : "r"(a[mi][0]), "r"(a[mi][1]), "r"(a[mi][2]), "r"(a[mi][3]),
                          "r"(b0), "r"(b1));
                }
            }
        }
        __syncthreads();
    }

    // ---- epilogue: attention dots, direct global store ----
#pragma unroll
    for (int mi = 0; mi < 2; mi++) {
        float ps[2][2] = {{0.f, 0.f}, {0.f, 0.f}};
        float pd[2][2] = {{0.f, 0.f}, {0.f, 0.f}};
#pragma unroll
        for (int ni = 0; ni < 8; ni++) {
            int col = wc * 64 + ni * 8 + 2 * t;
            float s0 = att_s[col], s1 = att_s[col + 1];
            float dd0 = att_d[col], dd1 = att_d[col + 1];
            int hl = ni >> 2;
            ps[0][hl] += acc[mi][ni][0] * s0 + acc[mi][ni][1] * s1;
            ps[1][hl] += acc[mi][ni][2] * s0 + acc[mi][ni][3] * s1;
            pd[0][hl] += acc[mi][ni][0] * dd0 + acc[mi][ni][1] * dd1;
            pd[1][hl] += acc[mi][ni][2] * dd0 + acc[mi][ni][3] * dd1;
        }
#pragma unroll
        for (int o = 1; o <= 2; o <<= 1) {
#pragma unroll
            for (int rh = 0; rh < 2; rh++)
#pragma unroll
                for (int hl = 0; hl < 2; hl++) {
                    ps[rh][hl] += __shfl_xor_sync(0xffffffffu, ps[rh][hl], o);
                    pd[rh][hl] += __shfl_xor_sync(0xffffffffu, pd[rh][hl], o);
                }
        }
        if (t == 0) {
            int gr = rowBase + wr * 32 + mi * 16 + g;
            if (gr < nrows) {
                d_ASRC[gr * 4 + 2 * wc]     = ps[0][0];
                d_ASRC[gr * 4 + 2 * wc + 1] = ps[0][1];
                d_ADST[gr * 4 + 2 * wc]     = pd[0][0];
                d_ADST[gr * 4 + 2 * wc + 1] = pd[0][1];
            }
            if (gr + 8 < nrows) {
                d_ASRC[(gr + 8) * 4 + 2 * wc]     = ps[1][0];
                d_ASRC[(gr + 8) * 4 + 2 * wc + 1] = ps[1][1];
                d_ADST[(gr + 8) * 4 + 2 * wc]     = pd[1][0];
                d_ADST[(gr + 8) * 4 + 2 * wc + 1] = pd[1][1];
            }
        }
    }
#pragma unroll
    for (int mi = 0; mi < 2; mi++) {
        int r0 = rowBase + wr * 32 + mi * 16 + g;
#pragma unroll
        for (int ni = 0; ni < 8; ni++) {
            int cp = wc * 32 + ni * 4 + t;
            if (r0 < nrows)
                d_XHh[r0 * 64 + cp] = __floats2half2_rn(acc[mi][ni][0], acc[mi][ni][1]);
            if (r0 + 8 < nrows)
                d_XHh[(r0 + 8) * 64 + cp] = __floats2half2_rn(acc[mi][ni][2], acc[mi][ni][3]);
        }
    }
}

// ---------------- CSR build: 4 edges/thread ----------------
template <bool V4>
__global__ void k_deg(const int* __restrict__ ei, int E) {
    int i = blockIdx.x * blockDim.x + threadIdx.x;
    if (V4) {
        int nv = E >> 2;
        if (i < nv) {
            int4 d4 = *(const int4*)&ei[E + i * 4];
            atomicAdd(&d_deg[d4.x], 1);
            atomicAdd(&d_deg[d4.y], 1);
            atomicAdd(&d_deg[d4.z], 1);
            atomicAdd(&d_deg[d4.w], 1);
        } else if (i == nv) {
            for (int j = nv * 4; j < E; j++) atomicAdd(&d_deg[ei[E + j]], 1);
        }
    } else {
        if (i < E) atomicAdd(&d_deg[ei[E + i]], 1);
    }
}

__global__ void __launch_bounds__(1024) k_scan1(int N) {
    __shared__ int swarp[32];
    int b = blockIdx.x;
    int tid = threadIdx.x, lane = tid & 31, wid = tid >> 5;
    int i = b * 1024 + tid;
    int v = (i < N) ? d_deg[i] : 0;
    int x = v;
#pragma unroll
    for (int o = 1; o < 32; o <<= 1) {
        int t = __shfl_up_sync(0xffffffffu, x, o);
        if (lane >= o) x += t;
    }
    if (lane == 31) swarp[wid] = x;
    __syncthreads();
    if (wid == 0) {
        int y = swarp[lane];
#pragma unroll
        for (int o = 1; o < 32; o <<= 1) {
            int t = __shfl_up_sync(0xffffffffu, y, o);
            if (lane >= o) y += t;
        }
        swarp[lane] = y;
    }
    __syncthreads();
    int incl = x + (wid > 0 ? swarp[wid - 1] : 0);
    if (i < N) d_rowptr[i + 1] = incl;
    if (tid == 1023) d_bsum[b] = incl;
}

// fused phase 2+3: full-warp 64-wide scan; also places self-loop col entry
__global__ void __launch_bounds__(1024) k_scan3(int N) {
    __shared__ int s_incl[64];
    int b = blockIdx.x;
    int nb = gridDim.x;
    int tid = threadIdx.x;
    if (tid < 64) {
        int v = (tid < nb) ? d_bsum[tid] : 0;
        int x = v;
#pragma unroll
        for (int o = 1; o < 32; o <<= 1) {
            int t = __shfl_up_sync(0xffffffffu, x, o);
            if ((tid & 31) >= o) x += t;
        }
        s_incl[tid] = x;
    }
    __syncthreads();
    int base = (b < 32) ? 0 : s_incl[31];
    int off = base + s_incl[b] - d_bsum[b];
    int i = b * 1024 + tid;
    if (i >= N) return;
    int rp = d_rowptr[i + 1] + off;
    d_rowptr[i + 1] = rp;
    d_cursor[i] = rp - d_deg[i];
    d_col[rp - 1] = i;                 // self loop takes guaranteed-last slot
    if (i == 0) d_rowptr[0] = 0;
}

template <bool V4>
__global__ void k_fill(const int* __restrict__ ei, int E) {
    int i = blockIdx.x * blockDim.x + threadIdx.x;
    if (V4) {
        int nv = E >> 2;
        if (i < nv) {
            int4 s4 = *(const int4*)&ei[i * 4];
            int4 d4 = *(const int4*)&ei[E + i * 4];
            int p0 = atomicAdd(&d_cursor[d4.x], 1);
            int p1 = atomicAdd(&d_cursor[d4.y], 1);
            int p2 = atomicAdd(&d_cursor[d4.z], 1);
            int p3 = atomicAdd(&d_cursor[d4.w], 1);
            d_col[p0] = s4.x; d_col[p1] = s4.y; d_col[p2] = s4.z; d_col[p3] = s4.w;
        } else if (i == nv) {
            for (int j = nv * 4; j < E; j++) {
                int pos = atomicAdd(&d_cursor[ei[E + j]], 1);
                d_col[pos] = ei[j];
            }
        }
    } else {
        if (i < E) {
            int pos = atomicAdd(&d_cursor[ei[E + i]], 1);
            d_col[pos] = ei[i];
        }
    }
}

// ---------------- GAT aggregation: warp per node; exp hoisted out of j-loop ----------------
template <bool LAYER2>
__global__ void __launch_bounds__(128) k_agg(
    const float* __restrict__ bias, void* __restrict__ OUT,
    const int* __restrict__ batch, int N)
{
    __shared__ float4 s_p4[4][32];
    __shared__ int    s_src[4][32];
    __shared__ float  s_out[4][32];
    __shared__ int    s_b[4];

    int tid = threadIdx.x;
    int w = tid >> 5, lane = tid & 31;
    int n = blockIdx.x * 4 + w;
    bool valid = (n < N);
    if (!LAYER2 && !valid) return;
    int h = lane >> 3;

    if (valid) {
        int start = d_rowptr[n], end = d_rowptr[n + 1];
        float4 ad = ((const float4*)d_ADST)[n];

        float4 m4 = make_float4(-INFINITY, -INFINITY, -INFINITY, -INFINITY);
        float den = 0.f;
        float4 acc = make_float4(0.f, 0.f, 0.f, 0.f);
        const float* sp = (const float*)&s_p4[w][0];
        const int*   ss = &s_src[w][0];
        const uint2* XH8 = (const uint2*)d_XHh;

        for (int k0 = start; k0 < end; k0 += 32) {
            int len = min(32, end - k0);
            float4 e4 = make_float4(-INFINITY, -INFINITY, -INFINITY, -INFINITY);
            int s = 0;
            if (lane < len) {
                s = __ldg(&d_col[k0 + lane]);
                float4 as = __ldg(&((const float4*)d_ASRC)[s]);
                e4.x = as.x + ad.x; e4.x = e4.x > 0.f ? e4.x : 0.2f * e4.x;
                e4.y = as.y + ad.y; e4.y = e4.y > 0.f ? e4.y : 0.2f * e4.y;
                e4.z = as.z + ad.z; e4.z = e4.z > 0.f ? e4.z : 0.2f * e4.z;
                e4.w = as.w + ad.w; e4.w = e4.w > 0.f ? e4.w : 0.2f * e4.w;
            }
            s_src[w][lane] = s;

            // chunk max per head (warp reduction)
            float4 mx = e4;
#pragma unroll
            for (int o = 16; o >= 1; o >>= 1) {
                mx.x = fmaxf(mx.x, __shfl_xor_sync(0xffffffffu, mx.x, o));
                mx.y = fmaxf(mx.y, __shfl_xor_sync(0xffffffffu, mx.y, o));
                mx.z = fmaxf(mx.z, __shfl_xor_sync(0xffffffffu, mx.z, o));
                mx.w = fmaxf(mx.w, __shfl_xor_sync(0xffffffffu, mx.w, o));
            }
            float4 cm4 = make_float4(fmaxf(m4.x, mx.x), fmaxf(m4.y, mx.y),
                                     fmaxf(m4.z, mx.z), fmaxf(m4.w, mx.w));
            float mh  = (h == 0) ? m4.x  : (h == 1) ? m4.y  : (h == 2) ? m4.z  : m4.w;
            float cmh = (h == 0) ? cm4.x : (h == 1) ? cm4.y : (h == 2) ? cm4.z : cm4.w;
            float scale = __expf(mh - cmh);
            acc.x *= scale; acc.y *= scale; acc.z *= scale; acc.w *= scale;
            den *= scale;

            // one exp per (lane, head); invalid lanes give exp(-inf)=0
            float4 p4;
            p4.x = __expf(e4.x - cm4.x);
            p4.y = __expf(e4.y - cm4.y);
            p4.z = __expf(e4.z - cm4.z);
            p4.w = __expf(e4.w - cm4.w);
            s_p4[w][lane] = p4;

            // den increment via warp sum (removes serial den chain from j-loop)
            float4 ds = p4;
#pragma unroll
            for (int o = 16; o >= 1; o >>= 1) {
                ds.x += __shfl_xor_sync(0xffffffffu, ds.x, o);
                ds.y += __shfl_xor_sync(0xffffffffu, ds.y, o);
                ds.z += __shfl_xor_sync(0xffffffffu, ds.z, o);
                ds.w += __shfl_xor_sync(0xffffffffu, ds.w, o);
            }
            den += (h == 0) ? ds.x : (h == 1) ? ds.y : (h == 2) ? ds.z : ds.w;

            __syncwarp();
#pragma unroll 4
            for (int j = 0; j < len; j++) {
                float p = sp[j * 4 + h];
                uint2 r = __ldg(&XH8[ss[j] * 32 + lane]);
                float2 f0 = __half22float2(*(const __half2*)&r.x);
                float2 f1 = __half22float2(*(const __half2*)&r.y);
                acc.x = fmaf(p, f0.x, acc.x);
                acc.y = fmaf(p, f0.y, acc.y);
                acc.z = fmaf(p, f1.x, acc.z);
                acc.w = fmaf(p, f1.y, acc.w);
            }
            m4 = cm4;
            __syncwarp();
        }

        float inv = 1.f / (den + 1e-16f);
        float4 val = make_float4(acc.x * inv, acc.y * inv, acc.z * inv, acc.w * inv);

        if (!LAYER2) {
            float4 b4 = ((const float4*)bias)[lane];
            val.x = fmaxf(val.x + b4.x, 0.f);
            val.y = fmaxf(val.y + b4.y, 0.f);
            val.z = fmaxf(val.z + b4.z, 0.f);
            val.w = fmaxf(val.w + b4.w, 0.f);
            __half2 h0 = __floats2half2_rn(val.x, val.y);
            __half2 h1 = __floats2half2_rn(val.z, val.w);
            uint2 p; p.x = *(uint32_t*)&h0; p.y = *(uint32_t*)&h1;
            ((uint2*)OUT)[n * 32 + lane] = p;     // fp16 H1
        } else {
#pragma unroll
            for (int o = 8; o <= 16; o <<= 1) {
                val.x += __shfl_xor_sync(0xffffffffu, val.x, o);
                val.y += __shfl_xor_sync(0xffffffffu, val.y, o);
                val.z += __shfl_xor_sync(0xffffffffu, val.z, o);
                val.w += __shfl_xor_sync(0xffffffffu, val.w, o);
            }
            if (lane < 8) {
                float4 b4 = ((const float4*)bias)[lane];
                s_out[w][lane * 4 + 0] = 0.25f * val.x + b4.x;
                s_out[w][lane * 4 + 1] = 0.25f * val.y + b4.y;
                s_out[w][lane * 4 + 2] = 0.25f * val.z + b4.z;
                s_out[w][lane * 4 + 3] = 0.25f * val.w + b4.w;
            }
            if (lane == 0) s_b[w] = batch[n];
        }
    } else if (LAYER2 && lane == 0) {
        s_b[w] = -1;
    }

    if (LAYER2) {
        __syncthreads();
        if (tid < 32) {
            float sum = 0.f;
            int curb = -1;
#pragma unroll
            for (int w2 = 0; w2 < 4; w2++) {
                int b = s_b[w2];
                if (b < 0) continue;
                if (b != curb) {
                    if (curb >= 0) atomicAdd(&d_gsum[curb * 32 + tid], sum);
                    curb = b; sum = 0.f;
                }
                sum += s_out[w2][tid];
            }
            if (curb >= 0) atomicAdd(&d_gsum[curb * 32 + tid], sum);
        }
    }
}

// ---------------- final MLP ----------------
__global__ void k_mlp(const int* __restrict__ batch, int N,
                      const float* __restrict__ stats,
                      const float* __restrict__ Wm1, const float* __restrict__ bm1,
                      const float* __restrict__ Wm2, const float* __restrict__ bm2,
                      float* __restrict__ out, int B)
{
    int g = threadIdx.x;
    if (g >= B) return;
    int lo0 = 0, hi0 = N;
    while (lo0 < hi0) { int mid = (lo0 + hi0) >> 1; if (batch[mid] < g) lo0 = mid + 1; else hi0 = mid; }
    int lo1 = lo0, hi1 = N;
    while (lo1 < hi1) { int mid = (lo1 + hi1) >> 1; if (batch[mid] < g + 1) lo1 = mid + 1; else hi1 = mid; }
    float cnt = (float)(lo1 - lo0);
    float inv = 1.f / fmaxf(cnt, 1.f);

    float v[47];
#pragma unroll
    for (int cc = 0; cc < 32; cc++) v[cc] = d_gsum[g * 32 + cc] * inv;
#pragma unroll
    for (int f = 0; f < 15; f++) v[32 + f] = stats[g * 15 + f];
    float o = bm2[0];
    for (int k = 0; k < 32; k++) {
        float hsum = bm1[k];
#pragma unroll
        for (int i = 0; i < 47; i++) hsum = fmaf(v[i], Wm1[i * 32 + k], hsum);
        o = fmaf(fmaxf(hsum, 0.f), Wm2[k], o);
    }
    out[g] = o;
}

// ---------------- launch ----------------
extern "C" void kernel_launch(void* const* d_in, const int* in_sizes, int n_in,
                              void* d_out, int out_size)
{
    const float* x     = (const float*)d_in[0];
    const int*   ei    = (const int*)d_in[1];
    const int*   batch = (const int*)d_in[2];
    const float* stats = (const float*)d_in[3];
    const float* W1    = (const float*)d_in[4];
    const float* as1   = (const float*)d_in[5];
    const float* ad1   = (const float*)d_in[6];
    const float* b1    = (const float*)d_in[7];
    const float* W2    = (const float*)d_in[8];
    const float* as2   = (const float*)d_in[9];
    const float* ad2   = (const float*)d_in[10];
    const float* b2    = (const float*)d_in[11];
    const float* Wm1   = (const float*)d_in[12];
    const float* bm1   = (const float*)d_in[13];
    const float* Wm2   = (const float*)d_in[14];
    const float* bm2   = (const float*)d_in[15];

    int N = in_sizes[0] / 128;
    int E = in_sizes[1] / 2;
    int B = in_sizes[3] / 15;

    __half *Wt1, *Wt2; __half2 *H1h;
    cudaGetSymbolAddress((void**)&Wt1, d_Wt1);
    cudaGetSymbolAddress((void**)&Wt2, d_Wt2);
    cudaGetSymbolAddress((void**)&H1h, d_H1h);

    int gemmBlocks = (N + 127) / 128;
    int aggBlocks  = (N + 3) / 4;
    int scanBlocks = (N + 1023) / 1024;
    bool v4 = ((E & 3) == 0);
    int edgeThreads = v4 ? (E / 4 + 1) : E;
    int edgeBlocks  = (edgeThreads + 255) / 256;

    k_init<<<128, 256>>>(W1, W2, N, B);

    if (v4) k_deg<true><<<edgeBlocks, 256>>>(ei, E);
    else    k_deg<false><<<edgeBlocks, 256>>>(ei, E);
    k_scan1<<<scanBlocks, 1024>>>(N);
    k_scan3<<<scanBlocks, 1024>>>(N);
    if (v4) k_fill<true><<<edgeBlocks, 256>>>(ei, E);
    else    k_fill<false><<<edgeBlocks, 256>>>(ei, E);

    k_gemm_att<false><<<gemmBlocks, 256>>>(x, Wt1, as1, ad1, N);
    k_agg<false><<<aggBlocks, 128>>>(b1, H1h, batch, N);

    k_gemm_att<true><<<gemmBlocks, 256>>>(H1h, Wt2, as2, ad2, N);
    k_agg<true><<<aggBlocks, 128>>>(b2, nullptr, batch, N);

    k_mlp<<<1, 128>>>(batch, N, stats, Wm1, bm1, Wm2, bm2, (float*)d_out, B);
}

// round 15
// speedup vs baseline: 1.0898x; 1.0898x over previous
#include <cuda_runtime.h>
#include <cuda_fp16.h>
#include <stdint.h>
#include <math.h>

#define NMAX 50000
#define EMAX 800000
#define BMAX 128

// ---------------- scratch ----------------
__device__ __half2 d_XHh [NMAX * 64];    // GEMM output fp16
__device__ __half2 d_H1h [NMAX * 64];    // layer-1 output fp16
__device__ __half  d_Wt1 [128 * 128];    // W1^T fp16 [n][k]
__device__ __half  d_Wt2 [128 * 128];    // W2^T fp16 [n][k]
__device__ float   d_ASRC[NMAX * 4];
__device__ float   d_ADST[NMAX * 4];
__device__ int     d_deg   [NMAX];
__device__ int     d_rowptr[NMAX + 1];
__device__ int     d_cursor[NMAX];
__device__ int     d_col   [EMAX + NMAX];
__device__ float   d_gsum  [BMAX * 32];
__device__ int     d_bsum  [64];

// ---------------- init + weight prep ----------------
__global__ void k_init(const float* __restrict__ W1, const float* __restrict__ W2,
                       int N, int B) {
    int i0 = blockIdx.x * blockDim.x + threadIdx.x;
    int stride = gridDim.x * blockDim.x;
    for (int t = i0; t < N; t += stride) d_deg[t] = 1;   // self loop pre-counted
    for (int t = i0; t < B * 32; t += stride) d_gsum[t] = 0.f;
    for (int t = i0; t < 16384; t += stride) {
        int n = t >> 7, k = t & 127;
        d_Wt1[n * 128 + k] = __float2half_rn(W1[k * 128 + n]);
        d_Wt2[n * 128 + k] = __float2half_rn(W2[k * 128 + n]);
    }
}

// ---------------- tensor-core GEMM + fused attention dots ----------------
template <bool HIN>
__global__ void __launch_bounds__(256, 2) k_gemm_att(
    const void* __restrict__ Xv, const __half* __restrict__ Wt,
    const float* __restrict__ att_s, const float* __restrict__ att_d,
    int nrows)
{
    __shared__ __half Xs[128][40];
    __shared__ __half Ws[128][40];

    int tid = threadIdx.x;
    int wid = tid >> 5, lane = tid & 31;
    int g = lane >> 2, t = lane & 3;
    int wr = wid >> 1, wc = wid & 1;
    int rowBase = blockIdx.x * 128;

    float acc[2][8][4];
#pragma unroll
    for (int mi = 0; mi < 2; mi++)
#pragma unroll
        for (int ni = 0; ni < 8; ni++)
#pragma unroll
            for (int q = 0; q < 4; q++) acc[mi][ni][q] = 0.f;

    for (int k0 = 0; k0 < 128; k0 += 32) {
        if (HIN) {
            const uint4* Xh = (const uint4*)Xv;
#pragma unroll
            for (int it = 0; it < 2; it++) {
                int idx = tid + 256 * it;
                int r = idx >> 2;
                int c8 = (idx & 3) * 8;
                int gr = rowBase + r;
                uint4 v = (gr < nrows) ? Xh[gr * 16 + (k0 >> 3) + (c8 >> 3)]
                                       : make_uint4(0u, 0u, 0u, 0u);
                *(uint4*)&Xs[r][c8] = v;
            }
        } else {
            const float* X = (const float*)Xv;
#pragma unroll
            for (int it = 0; it < 4; it++) {
                int idx = tid + 256 * it;
                int r = idx >> 3;
                int c4 = (idx & 7) * 4;
                int gr = rowBase + r;
                float4 v = (gr < nrows) ? *(const float4*)&X[gr * 128 + k0 + c4]
                                        : make_float4(0.f, 0.f, 0.f, 0.f);
                __half2 h0 = __floats2half2_rn(v.x, v.y);
                __half2 h1 = __floats2half2_rn(v.z, v.w);
                uint2 p; p.x = *(uint32_t*)&h0; p.y = *(uint32_t*)&h1;
                *(uint2*)&Xs[r][c4] = p;
            }
        }
#pragma unroll
        for (int it = 0; it < 2; it++) {
            int idx = tid + 256 * it;
            int n = idx >> 2;
            int c8 = (idx & 3) * 8;
            *(uint4*)&Ws[n][c8] = *(const uint4*)&Wt[n * 128 + k0 + c8];
        }
        __syncthreads();
#pragma unroll
        for (int ks = 0; ks < 2; ks++) {
            int kb = ks * 16;
            uint32_t a[2][4];
#pragma unroll
            for (int mi = 0; mi < 2; mi++) {
                int ar = wr * 32 + mi * 16 + g;
                a[mi][0] = *(const uint32_t*)&Xs[ar][kb + 2 * t];
                a[mi][1] = *(const uint32_t*)&Xs[ar + 8][kb + 2 * t];
                a[mi][2] = *(const uint32_t*)&Xs[ar][kb + 2 * t + 8];
                a[mi][3] = *(const uint32_t*)&Xs[ar + 8][kb + 2 * t + 8];
            }
#pragma unroll
            for (int ni = 0; ni < 8; ni++) {
                int bn = wc * 64 + ni * 8 + g;
                uint32_t b0 = *(const uint32_t*)&Ws[bn][kb + 2 * t];
                uint32_t b1 = *(const uint32_t*)&Ws[bn][kb + 2 * t + 8];
#pragma unroll
                for (int mi = 0; mi < 2; mi++) {
                    asm volatile(
                        "mma.sync.aligned.m16n8k16.row.col.f32.f16.f16.f32 "
                        "{%0,%1,%2,%3}, {%4,%5,%6,%7}, {%8,%9}, {%0,%1,%2,%3};"
                        : "+f"(acc[mi][ni][0]), "+f"(acc[mi][ni][1]),
                          "+f"(acc[mi][ni][2]), "+f"(acc[mi][ni][3])
                        : "r"(a[mi][0]), "r"(a[mi][1]), "r"(a[mi][2]), "r"(a[mi][3]),
                          "r"(b0), "r"(b1));
                }
            }
        }
        __syncthreads();
    }

    // ---- epilogue: attention dots, direct global store ----
#pragma unroll
    for (int mi = 0; mi < 2; mi++) {
        float ps[2][2] = {{0.f, 0.f}, {0.f, 0.f}};
        float pd[2][2] = {{0.f, 0.f}, {0.f, 0.f}};
#pragma unroll
        for (int ni = 0; ni < 8; ni++) {
            int col = wc * 64 + ni * 8 + 2 * t;
            float s0 = att_s[col], s1 = att_s[col + 1];
            float dd0 = att_d[col], dd1 = att_d[col + 1];
            int hl = ni >> 2;
            ps[0][hl] += acc[mi][ni][0] * s0 + acc[mi][ni][1] * s1;
            ps[1][hl] += acc[mi][ni][2] * s0 + acc[mi][ni][3] * s1;
            pd[0][hl] += acc[mi][ni][0] * dd0 + acc[mi][ni][1] * dd1;
            pd[1][hl] += acc[mi][ni][2] * dd0 + acc[mi][ni][3] * dd1;
        }
#pragma unroll
        for (int o = 1; o <= 2; o <<= 1) {
#pragma unroll
            for (int rh = 0; rh < 2; rh++)
#pragma unroll
                for (int hl = 0; hl < 2; hl++) {
                    ps[rh][hl] += __shfl_xor_sync(0xffffffffu, ps[rh][hl], o);
                    pd[rh][hl] += __shfl_xor_sync(0xffffffffu, pd[rh][hl], o);
                }
        }
        if (t == 0) {
            int gr = rowBase + wr * 32 + mi * 16 + g;
            if (gr < nrows) {
                d_ASRC[gr * 4 + 2 * wc]     = ps[0][0];
                d_ASRC[gr * 4 + 2 * wc + 1] = ps[0][1];
                d_ADST[gr * 4 + 2 * wc]     = pd[0][0];
                d_ADST[gr * 4 + 2 * wc + 1] = pd[0][1];
            }
            if (gr + 8 < nrows) {
                d_ASRC[(gr + 8) * 4 + 2 * wc]     = ps[1][0];
                d_ASRC[(gr + 8) * 4 + 2 * wc + 1] = ps[1][1];
                d_ADST[(gr + 8) * 4 + 2 * wc]     = pd[1][0];
                d_ADST[(gr + 8) * 4 + 2 * wc + 1] = pd[1][1];
            }
        }
    }
#pragma unroll
    for (int mi = 0; mi < 2; mi++) {
        int r0 = rowBase + wr * 32 + mi * 16 + g;
#pragma unroll
        for (int ni = 0; ni < 8; ni++) {
            int cp = wc * 32 + ni * 4 + t;
            if (r0 < nrows)
                d_XHh[r0 * 64 + cp] = __floats2half2_rn(acc[mi][ni][0], acc[mi][ni][1]);
            if (r0 + 8 < nrows)
                d_XHh[(r0 + 8) * 64 + cp] = __floats2half2_rn(acc[mi][ni][2], acc[mi][ni][3]);
        }
    }
}

// ---------------- CSR build: 4 edges/thread ----------------
template <bool V4>
__global__ void k_deg(const int* __restrict__ ei, int E) {
    int i = blockIdx.x * blockDim.x + threadIdx.x;
    if (V4) {
        int nv = E >> 2;
        if (i < nv) {
            int4 d4 = *(const int4*)&ei[E + i * 4];
            atomicAdd(&d_deg[d4.x], 1);
            atomicAdd(&d_deg[d4.y], 1);
            atomicAdd(&d_deg[d4.z], 1);
            atomicAdd(&d_deg[d4.w], 1);
        } else if (i == nv) {
            for (int j = nv * 4; j < E; j++) atomicAdd(&d_deg[ei[E + j]], 1);
        }
    } else {
        if (i < E) atomicAdd(&d_deg[ei[E + i]], 1);
    }
}

__global__ void __launch_bounds__(1024) k_scan1(int N) {
    __shared__ int swarp[32];
    int b = blockIdx.x;
    int tid = threadIdx.x, lane = tid & 31, wid = tid >> 5;
    int i = b * 1024 + tid;
    int v = (i < N) ? d_deg[i] : 0;
    int x = v;
#pragma unroll
    for (int o = 1; o < 32; o <<= 1) {
        int t = __shfl_up_sync(0xffffffffu, x, o);
        if (lane >= o) x += t;
    }
    if (lane == 31) swarp[wid] = x;
    __syncthreads();
    if (wid == 0) {
        int y = swarp[lane];
#pragma unroll
        for (int o = 1; o < 32; o <<= 1) {
            int t = __shfl_up_sync(0xffffffffu, y, o);
            if (lane >= o) y += t;
        }
        swarp[lane] = y;
    }
    __syncthreads();
    int incl = x + (wid > 0 ? swarp[wid - 1] : 0);
    if (i < N) d_rowptr[i + 1] = incl;
    if (tid == 1023) d_bsum[b] = incl;
}

// fused phase 2+3: full-warp 64-wide scan; also places self-loop col entry
__global__ void __launch_bounds__(1024) k_scan3(int N) {
    __shared__ int s_incl[64];
    int b = blockIdx.x;
    int nb = gridDim.x;
    int tid = threadIdx.x;
    if (tid < 64) {
        int v = (tid < nb) ? d_bsum[tid] : 0;
        int x = v;
#pragma unroll
        for (int o = 1; o < 32; o <<= 1) {
            int t = __shfl_up_sync(0xffffffffu, x, o);
            if ((tid & 31) >= o) x += t;
        }
        s_incl[tid] = x;
    }
    __syncthreads();
    int base = (b < 32) ? 0 : s_incl[31];
    int off = base + s_incl[b] - d_bsum[b];
    int i = b * 1024 + tid;
    if (i >= N) return;
    int rp = d_rowptr[i + 1] + off;
    d_rowptr[i + 1] = rp;
    d_cursor[i] = rp - d_deg[i];
    d_col[rp - 1] = i;                 // self loop takes guaranteed-last slot
    if (i == 0) d_rowptr[0] = 0;
}

template <bool V4>
__global__ void k_fill(const int* __restrict__ ei, int E) {
    int i = blockIdx.x * blockDim.x + threadIdx.x;
    if (V4) {
        int nv = E >> 2;
        if (i < nv) {
            int4 s4 = *(const int4*)&ei[i * 4];
            int4 d4 = *(const int4*)&ei[E + i * 4];
            int p0 = atomicAdd(&d_cursor[d4.x], 1);
            int p1 = atomicAdd(&d_cursor[d4.y], 1);
            int p2 = atomicAdd(&d_cursor[d4.z], 1);
            int p3 = atomicAdd(&d_cursor[d4.w], 1);
            d_col[p0] = s4.x; d_col[p1] = s4.y; d_col[p2] = s4.z; d_col[p3] = s4.w;
        } else if (i == nv) {
            for (int j = nv * 4; j < E; j++) {
                int pos = atomicAdd(&d_cursor[ei[E + j]], 1);
                d_col[pos] = ei[j];
            }
        }
    } else {
        if (i < E) {
            int pos = atomicAdd(&d_cursor[ei[E + i]], 1);
            d_col[pos] = ei[i];
        }
    }
}

// ---------------- GAT aggregation (round-12 scalar-state version) ----------------
// LAYER2 fuses graph mean-pool: block-level run compression -> ~32 atomics/block
template <bool LAYER2>
__global__ void __launch_bounds__(128) k_agg(
    const float* __restrict__ bias, void* __restrict__ OUT,
    const int* __restrict__ batch, int N)
{
    __shared__ float4 s_e4[4][32];
    __shared__ int    s_src[4][32];
    __shared__ float  s_out[4][32];
    __shared__ int    s_b[4];

    int tid = threadIdx.x;
    int w = tid >> 5, lane = tid & 31;
    int n = blockIdx.x * 4 + w;
    bool valid = (n < N);
    if (!LAYER2 && !valid) return;
    int h = lane >> 3;

    if (valid) {
        int start = d_rowptr[n], end = d_rowptr[n + 1];
        float4 ad = ((const float4*)d_ADST)[n];

        float m = -INFINITY, den = 0.f;
        float4 acc = make_float4(0.f, 0.f, 0.f, 0.f);
        const float* se = (const float*)&s_e4[w][0];
        const int*   ss = &s_src[w][0];
        const uint2* XH8 = (const uint2*)d_XHh;

        for (int k0 = start; k0 < end; k0 += 32) {
            int len = min(32, end - k0);
            float4 e4 = make_float4(-INFINITY, -INFINITY, -INFINITY, -INFINITY);
            int s = 0;
            if (lane < len) {
                s = __ldg(&d_col[k0 + lane]);
                float4 as = __ldg(&((const float4*)d_ASRC)[s]);
                e4.x = as.x + ad.x; e4.x = e4.x > 0.f ? e4.x : 0.2f * e4.x;
                e4.y = as.y + ad.y; e4.y = e4.y > 0.f ? e4.y : 0.2f * e4.y;
                e4.z = as.z + ad.z; e4.z = e4.z > 0.f ? e4.z : 0.2f * e4.z;
                e4.w = as.w + ad.w; e4.w = e4.w > 0.f ? e4.w : 0.2f * e4.w;
            }
            s_src[w][lane] = s;
            s_e4[w][lane] = e4;

            float4 mx = e4;
#pragma unroll
            for (int o = 16; o >= 1; o >>= 1) {
                mx.x = fmaxf(mx.x, __shfl_xor_sync(0xffffffffu, mx.x, o));
                mx.y = fmaxf(mx.y, __shfl_xor_sync(0xffffffffu, mx.y, o));
                mx.z = fmaxf(mx.z, __shfl_xor_sync(0xffffffffu, mx.z, o));
                mx.w = fmaxf(mx.w, __shfl_xor_sync(0xffffffffu, mx.w, o));
            }
            float cmh = (h == 0) ? mx.x : (h == 1) ? mx.y : (h == 2) ? mx.z : mx.w;
            float cm = fmaxf(m, cmh);
            float scale = __expf(m - cm);
            acc.x *= scale; acc.y *= scale; acc.z *= scale; acc.w *= scale;
            den *= scale;

            __syncwarp();
#pragma unroll 4
            for (int j = 0; j < len; j++) {
                float p = __expf(se[j * 4 + h] - cm);
                den += p;
                uint2 r = __ldg(&XH8[ss[j] * 32 + lane]);
                float2 f0 = __half22float2(*(const __half2*)&r.x);
                float2 f1 = __half22float2(*(const __half2*)&r.y);
                acc.x = fmaf(p, f0.x, acc.x);
                acc.y = fmaf(p, f0.y, acc.y);
                acc.z = fmaf(p, f1.x, acc.z);
                acc.w = fmaf(p, f1.y, acc.w);
            }
            m = cm;
            __syncwarp();
        }

        float inv = 1.f / (den + 1e-16f);
        float4 val = make_float4(acc.x * inv, acc.y * inv, acc.z * inv, acc.w * inv);

        if (!LAYER2) {
            float4 b4 = ((const float4*)bias)[lane];
            val.x = fmaxf(val.x + b4.x, 0.f);
            val.y = fmaxf(val.y + b4.y, 0.f);
            val.z = fmaxf(val.z + b4.z, 0.f);
            val.w = fmaxf(val.w + b4.w, 0.f);
            __half2 h0 = __floats2half2_rn(val.x, val.y);
            __half2 h1 = __floats2half2_rn(val.z, val.w);
            uint2 p; p.x = *(uint32_t*)&h0; p.y = *(uint32_t*)&h1;
            ((uint2*)OUT)[n * 32 + lane] = p;     // fp16 H1
        } else {
#pragma unroll
            for (int o = 8; o <= 16; o <<= 1) {
                val.x += __shfl_xor_sync(0xffffffffu, val.x, o);
                val.y += __shfl_xor_sync(0xffffffffu, val.y, o);
                val.z += __shfl_xor_sync(0xffffffffu, val.z, o);
                val.w += __shfl_xor_sync(0xffffffffu, val.w, o);
            }
            if (lane < 8) {
                float4 b4 = ((const float4*)bias)[lane];
                s_out[w][lane * 4 + 0] = 0.25f * val.x + b4.x;
                s_out[w][lane * 4 + 1] = 0.25f * val.y + b4.y;
                s_out[w][lane * 4 + 2] = 0.25f * val.z + b4.z;
                s_out[w][lane * 4 + 3] = 0.25f * val.w + b4.w;
            }
            if (lane == 0) s_b[w] = batch[n];
        }
    } else if (LAYER2 && lane == 0) {
        s_b[w] = -1;
    }

    if (LAYER2) {
        __syncthreads();
        if (tid < 32) {
            float sum = 0.f;
            int curb = -1;
#pragma unroll
            for (int w2 = 0; w2 < 4; w2++) {
                int b = s_b[w2];
                if (b < 0) continue;
                if (b != curb) {
                    if (curb >= 0) atomicAdd(&d_gsum[curb * 32 + tid], sum);
                    curb = b; sum = 0.f;
                }
                sum += s_out[w2][tid];
            }
            if (curb >= 0) atomicAdd(&d_gsum[curb * 32 + tid], sum);
        }
    }
}

// ---------------- final MLP ----------------
__global__ void k_mlp(const int* __restrict__ batch, int N,
                      const float* __restrict__ stats,
                      const float* __restrict__ Wm1, const float* __restrict__ bm1,
                      const float* __restrict__ Wm2, const float* __restrict__ bm2,
                      float* __restrict__ out, int B)
{
    int g = threadIdx.x;
    if (g >= B) return;
    int lo0 = 0, hi0 = N;
    while (lo0 < hi0) { int mid = (lo0 + hi0) >> 1; if (batch[mid] < g) lo0 = mid + 1; else hi0 = mid; }
    int lo1 = lo0, hi1 = N;
    while (lo1 < hi1) { int mid = (lo1 + hi1) >> 1; if (batch[mid] < g + 1) lo1 = mid + 1; else hi1 = mid; }
    float cnt = (float)(lo1 - lo0);
    float inv = 1.f / fmaxf(cnt, 1.f);

    float v[47];
#pragma unroll
    for (int cc = 0; cc < 32; cc++) v[cc] = d_gsum[g * 32 + cc] * inv;
#pragma unroll
    for (int f = 0; f < 15; f++) v[32 + f] = stats[g * 15 + f];
    float o = bm2[0];
    for (int k = 0; k < 32; k++) {
        float hsum = bm1[k];
#pragma unroll
        for (int i = 0; i < 47; i++) hsum = fmaf(v[i], Wm1[i * 32 + k], hsum);
        o = fmaf(fmaxf(hsum, 0.f), Wm2[k], o);
    }
    out[g] = o;
}

// ---------------- launch ----------------
extern "C" void kernel_launch(void* const* d_in, const int* in_sizes, int n_in,
                              void* d_out, int out_size)
{
    const float* x     = (const float*)d_in[0];
    const int*   ei    = (const int*)d_in[1];
    const int*   batch = (const int*)d_in[2];
    const float* stats = (const float*)d_in[3];
    const float* W1    = (const float*)d_in[4];
    const float* as1   = (const float*)d_in[5];
    const float* ad1   = (const float*)d_in[6];
    const float* b1    = (const float*)d_in[7];
    const float* W2    = (const float*)d_in[8];
    const float* as2   = (const float*)d_in[9];
    const float* ad2   = (const float*)d_in[10];
    const float* b2    = (const float*)d_in[11];
    const float* Wm1   = (const float*)d_in[12];
    const float* bm1   = (const float*)d_in[13];
    const float* Wm2   = (const float*)d_in[14];
    const float* bm2   = (const float*)d_in[15];

    int N = in_sizes[0] / 128;
    int E = in_sizes[1] / 2;
    int B = in_sizes[3] / 15;

    __half *Wt1, *Wt2; __half2 *H1h;
    cudaGetSymbolAddress((void**)&Wt1, d_Wt1);
    cudaGetSymbolAddress((void**)&Wt2, d_Wt2);
    cudaGetSymbolAddress((void**)&H1h, d_H1h);

    int gemmBlocks = (N + 127) / 128;
    int aggBlocks  = (N + 3) / 4;
    int scanBlocks = (N + 1023) / 1024;
    bool v4 = ((E & 3) == 0);
    int edgeThreads = v4 ? (E / 4 + 1) : E;
    int edgeBlocks  = (edgeThreads + 255) / 256;

    k_init<<<128, 256>>>(W1, W2, N, B);

    if (v4) k_deg<true><<<edgeBlocks, 256>>>(ei, E);
    else    k_deg<false><<<edgeBlocks, 256>>>(ei, E);
    k_scan1<<<scanBlocks, 1024>>>(N);
    k_scan3<<<scanBlocks, 1024>>>(N);
    if (v4) k_fill<true><<<edgeBlocks, 256>>>(ei, E);
    else    k_fill<false><<<edgeBlocks, 256>>>(ei, E);

    k_gemm_att<false><<<gemmBlocks, 256>>>(x, Wt1, as1, ad1, N);
    k_agg<false><<<aggBlocks, 128>>>(b1, H1h, batch, N);

    k_gemm_att<true><<<gemmBlocks, 256>>>(H1h, Wt2, as2, ad2, N);
    k_agg<true><<<aggBlocks, 128>>>(b2, nullptr, batch, N);

    k_mlp<<<1, 128>>>(batch, N, stats, Wm1, bm1, Wm2, bm2, (float*)d_out, B);
}

// round 16
// speedup vs baseline: 1.1383x; 1.0445x over previous
#include <cuda_runtime.h>
#include <cuda_fp16.h>
#include <stdint.h>
#include <math.h>

#define NMAX 50000
#define EMAX 800000
#define BMAX 128

// ---------------- scratch ----------------
__device__ __half2 d_XHh [NMAX * 64];    // GEMM output fp16
__device__ __half2 d_H1h [NMAX * 64];    // layer-1 output fp16
__device__ __half  d_Wt1 [128 * 128];    // W1^T fp16 [n][k]
__device__ __half  d_Wt2 [128 * 128];    // W2^T fp16 [n][k]
__device__ float   d_ASRC[NMAX * 4];
__device__ float   d_ADST[NMAX * 4];
__device__ int     d_deg   [NMAX];
__device__ int     d_rowptr[NMAX + 1];
__device__ int     d_cursor[NMAX];
__device__ int     d_col   [EMAX + NMAX];
__device__ float   d_gsum  [BMAX * 32];
__device__ int     d_bsum  [64];

// ---------------- init split: weights (main stream) / graph scratch (side stream) ----------------
__global__ void k_init_w(const float* __restrict__ W1, const float* __restrict__ W2) {
    int i0 = blockIdx.x * blockDim.x + threadIdx.x;
    int stride = gridDim.x * blockDim.x;
    for (int t = i0; t < 16384; t += stride) {
        int n = t >> 7, k = t & 127;
        d_Wt1[n * 128 + k] = __float2half_rn(W1[k * 128 + n]);
        d_Wt2[n * 128 + k] = __float2half_rn(W2[k * 128 + n]);
    }
}

__global__ void k_init_g(int N, int B) {
    int i0 = blockIdx.x * blockDim.x + threadIdx.x;
    int stride = gridDim.x * blockDim.x;
    for (int t = i0; t < N; t += stride) d_deg[t] = 1;   // self loop pre-counted
    for (int t = i0; t < B * 32; t += stride) d_gsum[t] = 0.f;
}

// ---------------- tensor-core GEMM + fused attention dots ----------------
template <bool HIN>
__global__ void __launch_bounds__(256, 2) k_gemm_att(
    const void* __restrict__ Xv, const __half* __restrict__ Wt,
    const float* __restrict__ att_s, const float* __restrict__ att_d,
    int nrows)
{
    __shared__ __half Xs[128][40];
    __shared__ __half Ws[128][40];

    int tid = threadIdx.x;
    int wid = tid >> 5, lane = tid & 31;
    int g = lane >> 2, t = lane & 3;
    int wr = wid >> 1, wc = wid & 1;
    int rowBase = blockIdx.x * 128;

    float acc[2][8][4];
#pragma unroll
    for (int mi = 0; mi < 2; mi++)
#pragma unroll
        for (int ni = 0; ni < 8; ni++)
#pragma unroll
            for (int q = 0; q < 4; q++) acc[mi][ni][q] = 0.f;

    for (int k0 = 0; k0 < 128; k0 += 32) {
        if (HIN) {
            const uint4* Xh = (const uint4*)Xv;
#pragma unroll
            for (int it = 0; it < 2; it++) {
                int idx = tid + 256 * it;
                int r = idx >> 2;
                int c8 = (idx & 3) * 8;
                int gr = rowBase + r;
                uint4 v = (gr < nrows) ? Xh[gr * 16 + (k0 >> 3) + (c8 >> 3)]
                                       : make_uint4(0u, 0u, 0u, 0u);
                *(uint4*)&Xs[r][c8] = v;
            }
        } else {
            const float* X = (const float*)Xv;
#pragma unroll
            for (int it = 0; it < 4; it++) {
                int idx = tid + 256 * it;
                int r = idx >> 3;
                int c4 = (idx & 7) * 4;
                int gr = rowBase + r;
                float4 v = (gr < nrows) ? *(const float4*)&X[gr * 128 + k0 + c4]
                                        : make_float4(0.f, 0.f, 0.f, 0.f);
                __half2 h0 = __floats2half2_rn(v.x, v.y);
                __half2 h1 = __floats2half2_rn(v.z, v.w);
                uint2 p; p.x = *(uint32_t*)&h0; p.y = *(uint32_t*)&h1;
                *(uint2*)&Xs[r][c4] = p;
            }
        }
#pragma unroll
        for (int it = 0; it < 2; it++) {
            int idx = tid + 256 * it;
            int n = idx >> 2;
            int c8 = (idx & 3) * 8;
            *(uint4*)&Ws[n][c8] = *(const uint4*)&Wt[n * 128 + k0 + c8];
        }
        __syncthreads();
#pragma unroll
        for (int ks = 0; ks < 2; ks++) {
            int kb = ks * 16;
            uint32_t a[2][4];
#pragma unroll
            for (int mi = 0; mi < 2; mi++) {
                int ar = wr * 32 + mi * 16 + g;
                a[mi][0] = *(const uint32_t*)&Xs[ar][kb + 2 * t];
                a[mi][1] = *(const uint32_t*)&Xs[ar + 8][kb + 2 * t];
                a[mi][2] = *(const uint32_t*)&Xs[ar][kb + 2 * t + 8];
                a[mi][3] = *(const uint32_t*)&Xs[ar + 8][kb + 2 * t + 8];
            }
#pragma unroll
            for (int ni = 0; ni < 8; ni++) {
                int bn = wc * 64 + ni * 8 + g;
                uint32_t b0 = *(const uint32_t*)&Ws[bn][kb + 2 * t];
                uint32_t b1 = *(const uint32_t*)&Ws[bn][kb + 2 * t + 8];
#pragma unroll
                for (int mi = 0; mi < 2; mi++) {
                    asm volatile(
                        "mma.sync.aligned.m16n8k16.row.col.f32.f16.f16.f32 "
                        "{%0,%1,%2,%3}, {%4,%5,%6,%7}, {%8,%9}, {%0,%1,%2,%3};"
                        : "+f"(acc[mi][ni][0]), "+f"(acc[mi][ni][1]),
                          "+f"(acc[mi][ni][2]), "+f"(acc[mi][ni][3])
                        : "r"(a[mi][0]), "r"(a[mi][1]), "r"(a[mi][2]), "r"(a[mi][3]),
                          "r"(b0), "r"(b1));
                }
            }
        }
        __syncthreads();
    }

    // ---- epilogue: attention dots, direct global store ----
#pragma unroll
    for (int mi = 0; mi < 2; mi++) {
        float ps[2][2] = {{0.f, 0.f}, {0.f, 0.f}};
        float pd[2][2] = {{0.f, 0.f}, {0.f, 0.f}};
#pragma unroll
        for (int ni = 0; ni < 8; ni++) {
            int col = wc * 64 + ni * 8 + 2 * t;
            float s0 = att_s[col], s1 = att_s[col + 1];
            float dd0 = att_d[col], dd1 = att_d[col + 1];
            int hl = ni >> 2;
            ps[0][hl] += acc[mi][ni][0] * s0 + acc[mi][ni][1] * s1;
            ps[1][hl] += acc[mi][ni][2] * s0 + acc[mi][ni][3] * s1;
            pd[0][hl] += acc[mi][ni][0] * dd0 + acc[mi][ni][1] * dd1;
            pd[1][hl] += acc[mi][ni][2] * dd0 + acc[mi][ni][3] * dd1;
        }
#pragma unroll
        for (int o = 1; o <= 2; o <<= 1) {
#pragma unroll
            for (int rh = 0; rh < 2; rh++)
#pragma unroll
                for (int hl = 0; hl < 2; hl++) {
                    ps[rh][hl] += __shfl_xor_sync(0xffffffffu, ps[rh][hl], o);
                    pd[rh][hl] += __shfl_xor_sync(0xffffffffu, pd[rh][hl], o);
                }
        }
        if (t == 0) {
            int gr = rowBase + wr * 32 + mi * 16 + g;
            if (gr < nrows) {
                d_ASRC[gr * 4 + 2 * wc]     = ps[0][0];
                d_ASRC[gr * 4 + 2 * wc + 1] = ps[0][1];
                d_ADST[gr * 4 + 2 * wc]     = pd[0][0];
                d_ADST[gr * 4 + 2 * wc + 1] = pd[0][1];
            }
            if (gr + 8 < nrows) {
                d_ASRC[(gr + 8) * 4 + 2 * wc]     = ps[1][0];
                d_ASRC[(gr + 8) * 4 + 2 * wc + 1] = ps[1][1];
                d_ADST[(gr + 8) * 4 + 2 * wc]     = pd[1][0];
                d_ADST[(gr + 8) * 4 + 2 * wc + 1] = pd[1][1];
            }
        }
    }
#pragma unroll
    for (int mi = 0; mi < 2; mi++) {
        int r0 = rowBase + wr * 32 + mi * 16 + g;
#pragma unroll
        for (int ni = 0; ni < 8; ni++) {
            int cp = wc * 32 + ni * 4 + t;
            if (r0 < nrows)
                d_XHh[r0 * 64 + cp] = __floats2half2_rn(acc[mi][ni][0], acc[mi][ni][1]);
            if (r0 + 8 < nrows)
                d_XHh[(r0 + 8) * 64 + cp] = __floats2half2_rn(acc[mi][ni][2], acc[mi][ni][3]);
        }
    }
}

// ---------------- CSR build (round-12 scalar kernels) ----------------
__global__ void k_deg(const int* __restrict__ ei, int E) {
    int i = blockIdx.x * blockDim.x + threadIdx.x;
    if (i >= E) return;
    atomicAdd(&d_deg[ei[E + i]], 1);
}

__global__ void __launch_bounds__(1024) k_scan1(int N) {
    __shared__ int swarp[32];
    int b = blockIdx.x;
    int tid = threadIdx.x, lane = tid & 31, wid = tid >> 5;
    int i = b * 1024 + tid;
    int v = (i < N) ? d_deg[i] : 0;
    int x = v;
#pragma unroll
    for (int o = 1; o < 32; o <<= 1) {
        int t = __shfl_up_sync(0xffffffffu, x, o);
        if (lane >= o) x += t;
    }
    if (lane == 31) swarp[wid] = x;
    __syncthreads();
    if (wid == 0) {
        int y = swarp[lane];
#pragma unroll
        for (int o = 1; o < 32; o <<= 1) {
            int t = __shfl_up_sync(0xffffffffu, y, o);
            if (lane >= o) y += t;
        }
        swarp[lane] = y;
    }
    __syncthreads();
    int incl = x + (wid > 0 ? swarp[wid - 1] : 0);
    if (i < N) d_rowptr[i + 1] = incl;
    if (tid == 1023) d_bsum[b] = incl;
}

// fused phase 2+3: full-warp 64-wide scan
__global__ void __launch_bounds__(1024) k_scan3(int N) {
    __shared__ int s_incl[64];
    int b = blockIdx.x;
    int nb = gridDim.x;
    int tid = threadIdx.x;
    if (tid < 64) {
        int v = (tid < nb) ? d_bsum[tid] : 0;
        int x = v;
#pragma unroll
        for (int o = 1; o < 32; o <<= 1) {
            int t = __shfl_up_sync(0xffffffffu, x, o);
            if ((tid & 31) >= o) x += t;
        }
        s_incl[tid] = x;
    }
    __syncthreads();
    int base = (b < 32) ? 0 : s_incl[31];
    int off = base + s_incl[b] - d_bsum[b];
    int i = b * 1024 + tid;
    if (i >= N) return;
    int rp = d_rowptr[i + 1] + off;
    d_rowptr[i + 1] = rp;
    d_cursor[i] = rp - d_deg[i];
    if (i == 0) d_rowptr[0] = 0;
}

// edges via cursor atomic; self loop takes guaranteed-last slot (no atomic)
__global__ void k_fill(const int* __restrict__ ei, int E, int N) {
    int i = blockIdx.x * blockDim.x + threadIdx.x;
    int T = E + N;
    if (i >= T) return;
    if (i < E) {
        int s = ei[i], dd = ei[E + i];
        int pos = atomicAdd(&d_cursor[dd], 1);
        d_col[pos] = s;
    } else {
        int n = i - E;
        d_col[d_rowptr[n + 1] - 1] = n;
    }
}

// ---------------- GAT aggregation (round-12; LAYER2 fuses mean-pool) ----------------
template <bool LAYER2>
__global__ void __launch_bounds__(128) k_agg(
    const float* __restrict__ bias, void* __restrict__ OUT,
    const int* __restrict__ batch, int N)
{
    __shared__ float4 s_e4[4][32];
    __shared__ int    s_src[4][32];
    __shared__ float  s_out[4][32];
    __shared__ int    s_b[4];

    int tid = threadIdx.x;
    int w = tid >> 5, lane = tid & 31;
    int n = blockIdx.x * 4 + w;
    bool valid = (n < N);
    if (!LAYER2 && !valid) return;
    int h = lane >> 3;

    if (valid) {
        int start = d_rowptr[n], end = d_rowptr[n + 1];
        float4 ad = ((const float4*)d_ADST)[n];

        float m = -INFINITY, den = 0.f;
        float4 acc = make_float4(0.f, 0.f, 0.f, 0.f);
        const float* se = (const float*)&s_e4[w][0];
        const int*   ss = &s_src[w][0];
        const uint2* XH8 = (const uint2*)d_XHh;

        for (int k0 = start; k0 < end; k0 += 32) {
            int len = min(32, end - k0);
            float4 e4 = make_float4(-INFINITY, -INFINITY, -INFINITY, -INFINITY);
            int s = 0;
            if (lane < len) {
                s = __ldg(&d_col[k0 + lane]);
                float4 as = __ldg(&((const float4*)d_ASRC)[s]);
                e4.x = as.x + ad.x; e4.x = e4.x > 0.f ? e4.x : 0.2f * e4.x;
                e4.y = as.y + ad.y; e4.y = e4.y > 0.f ? e4.y : 0.2f * e4.y;
                e4.z = as.z + ad.z; e4.z = e4.z > 0.f ? e4.z : 0.2f * e4.z;
                e4.w = as.w + ad.w; e4.w = e4.w > 0.f ? e4.w : 0.2f * e4.w;
            }
            s_src[w][lane] = s;
            s_e4[w][lane] = e4;

            float4 mx = e4;
#pragma unroll
            for (int o = 16; o >= 1; o >>= 1) {
                mx.x = fmaxf(mx.x, __shfl_xor_sync(0xffffffffu, mx.x, o));
                mx.y = fmaxf(mx.y, __shfl_xor_sync(0xffffffffu, mx.y, o));
                mx.z = fmaxf(mx.z, __shfl_xor_sync(0xffffffffu, mx.z, o));
                mx.w = fmaxf(mx.w, __shfl_xor_sync(0xffffffffu, mx.w, o));
            }
            float cmh = (h == 0) ? mx.x : (h == 1) ? mx.y : (h == 2) ? mx.z : mx.w;
            float cm = fmaxf(m, cmh);
            float scale = __expf(m - cm);
            acc.x *= scale; acc.y *= scale; acc.z *= scale; acc.w *= scale;
            den *= scale;

            __syncwarp();
#pragma unroll 4
            for (int j = 0; j < len; j++) {
                float p = __expf(se[j * 4 + h] - cm);
                den += p;
                uint2 r = __ldg(&XH8[ss[j] * 32 + lane]);
                float2 f0 = __half22float2(*(const __half2*)&r.x);
                float2 f1 = __half22float2(*(const __half2*)&r.y);
                acc.x = fmaf(p, f0.x, acc.x);
                acc.y = fmaf(p, f0.y, acc.y);
                acc.z = fmaf(p, f1.x, acc.z);
                acc.w = fmaf(p, f1.y, acc.w);
            }
            m = cm;
            __syncwarp();
        }

        float inv = 1.f / (den + 1e-16f);
        float4 val = make_float4(acc.x * inv, acc.y * inv, acc.z * inv, acc.w * inv);

        if (!LAYER2) {
            float4 b4 = ((const float4*)bias)[lane];
            val.x = fmaxf(val.x + b4.x, 0.f);
            val.y = fmaxf(val.y + b4.y, 0.f);
            val.z = fmaxf(val.z + b4.z, 0.f);
            val.w = fmaxf(val.w + b4.w, 0.f);
            __half2 h0 = __floats2half2_rn(val.x, val.y);
            __half2 h1 = __floats2half2_rn(val.z, val.w);
            uint2 p; p.x = *(uint32_t*)&h0; p.y = *(uint32_t*)&h1;
            ((uint2*)OUT)[n * 32 + lane] = p;     // fp16 H1
        } else {
#pragma unroll
            for (int o = 8; o <= 16; o <<= 1) {
                val.x += __shfl_xor_sync(0xffffffffu, val.x, o);
                val.y += __shfl_xor_sync(0xffffffffu, val.y, o);
                val.z += __shfl_xor_sync(0xffffffffu, val.z, o);
                val.w += __shfl_xor_sync(0xffffffffu, val.w, o);
            }
            if (lane < 8) {
                float4 b4 = ((const float4*)bias)[lane];
                s_out[w][lane * 4 + 0] = 0.25f * val.x + b4.x;
                s_out[w][lane * 4 + 1] = 0.25f * val.y + b4.y;
                s_out[w][lane * 4 + 2] = 0.25f * val.z + b4.z;
                s_out[w][lane * 4 + 3] = 0.25f * val.w + b4.w;
            }
            if (lane == 0) s_b[w] = batch[n];
        }
    } else if (LAYER2 && lane == 0) {
        s_b[w] = -1;
    }

    if (LAYER2) {
        __syncthreads();
        if (tid < 32) {
            float sum = 0.f;
            int curb = -1;
#pragma unroll
            for (int w2 = 0; w2 < 4; w2++) {
                int b = s_b[w2];
                if (b < 0) continue;
                if (b != curb) {
                    if (curb >= 0) atomicAdd(&d_gsum[curb * 32 + tid], sum);
                    curb = b; sum = 0.f;
                }
                sum += s_out[w2][tid];
            }
            if (curb >= 0) atomicAdd(&d_gsum[curb * 32 + tid], sum);
        }
    }
}

// ---------------- final MLP ----------------
__global__ void k_mlp(const int* __restrict__ batch, int N,
                      const float* __restrict__ stats,
                      const float* __restrict__ Wm1, const float* __restrict__ bm1,
                      const float* __restrict__ Wm2, const float* __restrict__ bm2,
                      float* __restrict__ out, int B)
{
    int g = threadIdx.x;
    if (g >= B) return;
    int lo0 = 0, hi0 = N;
    while (lo0 < hi0) { int mid = (lo0 + hi0) >> 1; if (batch[mid] < g) lo0 = mid + 1; else hi0 = mid; }
    int lo1 = lo0, hi1 = N;
    while (lo1 < hi1) { int mid = (lo1 + hi1) >> 1; if (batch[mid] < g + 1) lo1 = mid + 1; else hi1 = mid; }
    float cnt = (float)(lo1 - lo0);
    float inv = 1.f / fmaxf(cnt, 1.f);

    float v[47];
#pragma unroll
    for (int cc = 0; cc < 32; cc++) v[cc] = d_gsum[g * 32 + cc] * inv;
#pragma unroll
    for (int f = 0; f < 15; f++) v[32 + f] = stats[g * 15 + f];
    float o = bm2[0];
    for (int k = 0; k < 32; k++) {
        float hsum = bm1[k];
#pragma unroll
        for (int i = 0; i < 47; i++) hsum = fmaf(v[i], Wm1[i * 32 + k], hsum);
        o = fmaf(fmaxf(hsum, 0.f), Wm2[k], o);
    }
    out[g] = o;
}

// ---------------- launch ----------------
extern "C" void kernel_launch(void* const* d_in, const int* in_sizes, int n_in,
                              void* d_out, int out_size)
{
    const float* x     = (const float*)d_in[0];
    const int*   ei    = (const int*)d_in[1];
    const int*   batch = (const int*)d_in[2];
    const float* stats = (const float*)d_in[3];
    const float* W1    = (const float*)d_in[4];
    const float* as1   = (const float*)d_in[5];
    const float* ad1   = (const float*)d_in[6];
    const float* b1    = (const float*)d_in[7];
    const float* W2    = (const float*)d_in[8];
    const float* as2   = (const float*)d_in[9];
    const float* ad2   = (const float*)d_in[10];
    const float* b2    = (const float*)d_in[11];
    const float* Wm1   = (const float*)d_in[12];
    const float* bm1   = (const float*)d_in[13];
    const float* Wm2   = (const float*)d_in[14];
    const float* bm2   = (const float*)d_in[15];

    int N = in_sizes[0] / 128;
    int E = in_sizes[1] / 2;
    int B = in_sizes[3] / 15;

    __half *Wt1, *Wt2; __half2 *H1h;
    cudaGetSymbolAddress((void**)&Wt1, d_Wt1);
    cudaGetSymbolAddress((void**)&Wt2, d_Wt2);
    cudaGetSymbolAddress((void**)&H1h, d_H1h);

    // side stream + events (host objects; created once)
    static cudaStream_t s_side = nullptr;
    static cudaEvent_t  s_ev0 = nullptr, s_ev1 = nullptr;
    if (!s_side) {
        cudaStreamCreateWithFlags(&s_side, cudaStreamNonBlocking);
        cudaEventCreateWithFlags(&s_ev0, cudaEventDisableTiming);
        cudaEventCreateWithFlags(&s_ev1, cudaEventDisableTiming);
    }

    int gemmBlocks = (N + 127) / 128;
    int edgeBlocks = (E + 255) / 256;
    int fillBlocks = (E + N + 255) / 256;
    int aggBlocks  = (N + 3) / 4;
    int scanBlocks = (N + 1023) / 1024;

    // fork: side stream handles graph init + CSR build (L2/atomic-bound, low occupancy)
    cudaEventRecord(s_ev0, 0);
    cudaStreamWaitEvent(s_side, s_ev0, 0);

    k_init_g<<<64, 256, 0, s_side>>>(N, B);
    k_deg  <<<edgeBlocks, 256, 0, s_side>>>(ei, E);
    k_scan1<<<scanBlocks, 1024, 0, s_side>>>(N);
    k_scan3<<<scanBlocks, 1024, 0, s_side>>>(N);
    k_fill <<<fillBlocks, 256, 0, s_side>>>(ei, E, N);
    cudaEventRecord(s_ev1, s_side);

    // main stream: weight prep + GEMM1 (tensor/smem-bound) co-runs with CSR chain
    k_init_w<<<64, 256>>>(W1, W2);
    k_gemm_att<false><<<gemmBlocks, 256>>>(x, Wt1, as1, ad1, N);

    cudaStreamWaitEvent(0, s_ev1, 0);   // join: agg needs CSR + GEMM1
    k_agg<false><<<aggBlocks, 128>>>(b1, H1h, batch, N);

    k_gemm_att<true><<<gemmBlocks, 256>>>(H1h, Wt2, as2, ad2, N);
    k_agg<true><<<aggBlocks, 128>>>(b2, nullptr, batch, N);

    k_mlp<<<1, 128>>>(batch, N, stats, Wm1, bm1, Wm2, bm2, (float*)d_out, B);
}

// round 17
// speedup vs baseline: 1.1524x; 1.0124x over previous
#include <cuda_runtime.h>
#include <cuda_fp16.h>
#include <stdint.h>
#include <math.h>

#define NMAX 50000
#define EMAX 800000
#define BMAX 128

// ---------------- scratch ----------------
__device__ __half2 d_XHh [NMAX * 64];    // GEMM output fp16
__device__ __half2 d_H1h [NMAX * 64];    // layer-1 output fp16
__device__ __half  d_Wt1 [128 * 128];    // W1^T fp16 [n][k]
__device__ __half  d_Wt2 [128 * 128];    // W2^T fp16 [n][k]
__device__ float   d_ASRC[NMAX * 4];
__device__ float   d_ADST[NMAX * 4];
__device__ int     d_deg   [NMAX];
__device__ int     d_rowptr[NMAX + 1];
__device__ int     d_cursor[NMAX];
__device__ int     d_col   [EMAX + NMAX];
__device__ float   d_gsum  [BMAX * 32];
__device__ int     d_bsum  [64];

// ---------------- init split: weights (main stream) / graph scratch (side stream) ----------------
__global__ void k_init_w(const float* __restrict__ W1, const float* __restrict__ W2) {
    int i0 = blockIdx.x * blockDim.x + threadIdx.x;
    int stride = gridDim.x * blockDim.x;
    for (int t = i0; t < 16384; t += stride) {
        int n = t >> 7, k = t & 127;
        d_Wt1[n * 128 + k] = __float2half_rn(W1[k * 128 + n]);
        d_Wt2[n * 128 + k] = __float2half_rn(W2[k * 128 + n]);
    }
}

__global__ void k_init_g(int N, int B) {
    int i0 = blockIdx.x * blockDim.x + threadIdx.x;
    int stride = gridDim.x * blockDim.x;
    for (int t = i0; t < N; t += stride) d_deg[t] = 1;   // self loop pre-counted
    for (int t = i0; t < B * 32; t += stride) d_gsum[t] = 0.f;
}

// ---------------- tensor-core GEMM + fused attention dots (persistent tile loop) ----------------
template <bool HIN>
__global__ void __launch_bounds__(256, 2) k_gemm_att(
    const void* __restrict__ Xv, const __half* __restrict__ Wt,
    const float* __restrict__ att_s, const float* __restrict__ att_d,
    int nrows, int numTiles)
{
    __shared__ __half Xs[128][40];
    __shared__ __half Ws[128][40];

    int tid = threadIdx.x;
    int wid = tid >> 5, lane = tid & 31;
    int g = lane >> 2, t = lane & 3;
    int wr = wid >> 1, wc = wid & 1;

    for (int tile = blockIdx.x; tile < numTiles; tile += gridDim.x) {
        int rowBase = tile * 128;

        float acc[2][8][4];
#pragma unroll
        for (int mi = 0; mi < 2; mi++)
#pragma unroll
            for (int ni = 0; ni < 8; ni++)
#pragma unroll
                for (int q = 0; q < 4; q++) acc[mi][ni][q] = 0.f;

        for (int k0 = 0; k0 < 128; k0 += 32) {
            if (HIN) {
                const uint4* Xh = (const uint4*)Xv;
#pragma unroll
                for (int it = 0; it < 2; it++) {
                    int idx = tid + 256 * it;
                    int r = idx >> 2;
                    int c8 = (idx & 3) * 8;
                    int gr = rowBase + r;
                    uint4 v = (gr < nrows) ? Xh[gr * 16 + (k0 >> 3) + (c8 >> 3)]
                                           : make_uint4(0u, 0u, 0u, 0u);
                    *(uint4*)&Xs[r][c8] = v;
                }
            } else {
                const float* X = (const float*)Xv;
#pragma unroll
                for (int it = 0; it < 4; it++) {
                    int idx = tid + 256 * it;
                    int r = idx >> 3;
                    int c4 = (idx & 7) * 4;
                    int gr = rowBase + r;
                    float4 v = (gr < nrows) ? *(const float4*)&X[gr * 128 + k0 + c4]
                                            : make_float4(0.f, 0.f, 0.f, 0.f);
                    __half2 h0 = __floats2half2_rn(v.x, v.y);
                    __half2 h1 = __floats2half2_rn(v.z, v.w);
                    uint2 p; p.x = *(uint32_t*)&h0; p.y = *(uint32_t*)&h1;
                    *(uint2*)&Xs[r][c4] = p;
                }
            }
#pragma unroll
            for (int it = 0; it < 2; it++) {
                int idx = tid + 256 * it;
                int n = idx >> 2;
                int c8 = (idx & 3) * 8;
                *(uint4*)&Ws[n][c8] = *(const uint4*)&Wt[n * 128 + k0 + c8];
            }
            __syncthreads();
#pragma unroll
            for (int ks = 0; ks < 2; ks++) {
                int kb = ks * 16;
                uint32_t a[2][4];
#pragma unroll
                for (int mi = 0; mi < 2; mi++) {
                    int ar = wr * 32 + mi * 16 + g;
                    a[mi][0] = *(const uint32_t*)&Xs[ar][kb + 2 * t];
                    a[mi][1] = *(const uint32_t*)&Xs[ar + 8][kb + 2 * t];
                    a[mi][2] = *(const uint32_t*)&Xs[ar][kb + 2 * t + 8];
                    a[mi][3] = *(const uint32_t*)&Xs[ar + 8][kb + 2 * t + 8];
                }
#pragma unroll
                for (int ni = 0; ni < 8; ni++) {
                    int bn = wc * 64 + ni * 8 + g;
                    uint32_t b0 = *(const uint32_t*)&Ws[bn][kb + 2 * t];
                    uint32_t b1 = *(const uint32_t*)&Ws[bn][kb + 2 * t + 8];
#pragma unroll
                    for (int mi = 0; mi < 2; mi++) {
                        asm volatile(
                            "mma.sync.aligned.m16n8k16.row.col.f32.f16.f16.f32 "
                            "{%0,%1,%2,%3}, {%4,%5,%6,%7}, {%8,%9}, {%0,%1,%2,%3};"
                            : "+f"(acc[mi][ni][0]), "+f"(acc[mi][ni][1]),
                              "+f"(acc[mi][ni][2]), "+f"(acc[mi][ni][3])
                            : "r"(a[mi][0]), "r"(a[mi][1]), "r"(a[mi][2]), "r"(a[mi][3]),
                              "r"(b0), "r"(b1));
                    }
                }
            }
            __syncthreads();
        }

        // ---- epilogue: attention dots, direct global store (registers/global only) ----
#pragma unroll
        for (int mi = 0; mi < 2; mi++) {
            float ps[2][2] = {{0.f, 0.f}, {0.f, 0.f}};
            float pd[2][2] = {{0.f, 0.f}, {0.f, 0.f}};
#pragma unroll
            for (int ni = 0; ni < 8; ni++) {
                int col = wc * 64 + ni * 8 + 2 * t;
                float s0 = att_s[col], s1 = att_s[col + 1];
                float dd0 = att_d[col], dd1 = att_d[col + 1];
                int hl = ni >> 2;
                ps[0][hl] += acc[mi][ni][0] * s0 + acc[mi][ni][1] * s1;
                ps[1][hl] += acc[mi][ni][2] * s0 + acc[mi][ni][3] * s1;
                pd[0][hl] += acc[mi][ni][0] * dd0 + acc[mi][ni][1] * dd1;
                pd[1][hl] += acc[mi][ni][2] * dd0 + acc[mi][ni][3] * dd1;
            }
#pragma unroll
            for (int o = 1; o <= 2; o <<= 1) {
#pragma unroll
                for (int rh = 0; rh < 2; rh++)
#pragma unroll
                    for (int hl = 0; hl < 2; hl++) {
                        ps[rh][hl] += __shfl_xor_sync(0xffffffffu, ps[rh][hl], o);
                        pd[rh][hl] += __shfl_xor_sync(0xffffffffu, pd[rh][hl], o);
                    }
            }
            if (t == 0) {
                int gr = rowBase + wr * 32 + mi * 16 + g;
                if (gr < nrows) {
                    d_ASRC[gr * 4 + 2 * wc]     = ps[0][0];
                    d_ASRC[gr * 4 + 2 * wc + 1] = ps[0][1];
                    d_ADST[gr * 4 + 2 * wc]     = pd[0][0];
                    d_ADST[gr * 4 + 2 * wc + 1] = pd[0][1];
                }
                if (gr + 8 < nrows) {
                    d_ASRC[(gr + 8) * 4 + 2 * wc]     = ps[1][0];
                    d_ASRC[(gr + 8) * 4 + 2 * wc + 1] = ps[1][1];
                    d_ADST[(gr + 8) * 4 + 2 * wc]     = pd[1][0];
                    d_ADST[(gr + 8) * 4 + 2 * wc + 1] = pd[1][1];
                }
            }
        }
#pragma unroll
        for (int mi = 0; mi < 2; mi++) {
            int r0 = rowBase + wr * 32 + mi * 16 + g;
#pragma unroll
            for (int ni = 0; ni < 8; ni++) {
                int cp = wc * 32 + ni * 4 + t;
                if (r0 < nrows)
                    d_XHh[r0 * 64 + cp] = __floats2half2_rn(acc[mi][ni][0], acc[mi][ni][1]);
                if (r0 + 8 < nrows)
                    d_XHh[(r0 + 8) * 64 + cp] = __floats2half2_rn(acc[mi][ni][2], acc[mi][ni][3]);
            }
        }
        // smem reuse is safe: last k-iteration ended with __syncthreads(), and
        // the epilogue touches only registers + global memory.
    }
}

// ---------------- CSR build (round-12 scalar kernels) ----------------
__global__ void k_deg(const int* __restrict__ ei, int E) {
    int i = blockIdx.x * blockDim.x + threadIdx.x;
    if (i >= E) return;
    atomicAdd(&d_deg[ei[E + i]], 1);
}

__global__ void __launch_bounds__(1024) k_scan1(int N) {
    __shared__ int swarp[32];
    int b = blockIdx.x;
    int tid = threadIdx.x, lane = tid & 31, wid = tid >> 5;
    int i = b * 1024 + tid;
    int v = (i < N) ? d_deg[i] : 0;
    int x = v;
#pragma unroll
    for (int o = 1; o < 32; o <<= 1) {
        int t = __shfl_up_sync(0xffffffffu, x, o);
        if (lane >= o) x += t;
    }
    if (lane == 31) swarp[wid] = x;
    __syncthreads();
    if (wid == 0) {
        int y = swarp[lane];
#pragma unroll
        for (int o = 1; o < 32; o <<= 1) {
            int t = __shfl_up_sync(0xffffffffu, y, o);
            if (lane >= o) y += t;
        }
        swarp[lane] = y;
    }
    __syncthreads();
    int incl = x + (wid > 0 ? swarp[wid - 1] : 0);
    if (i < N) d_rowptr[i + 1] = incl;
    if (tid == 1023) d_bsum[b] = incl;
}

// fused phase 2+3: full-warp 64-wide scan
__global__ void __launch_bounds__(1024) k_scan3(int N) {
    __shared__ int s_incl[64];
    int b = blockIdx.x;
    int nb = gridDim.x;
    int tid = threadIdx.x;
    if (tid < 64) {
        int v = (tid < nb) ? d_bsum[tid] : 0;
        int x = v;
#pragma unroll
        for (int o = 1; o < 32; o <<= 1) {
            int t = __shfl_up_sync(0xffffffffu, x, o);
            if ((tid & 31) >= o) x += t;
        }
        s_incl[tid] = x;
    }
    __syncthreads();
    int base = (b < 32) ? 0 : s_incl[31];
    int off = base + s_incl[b] - d_bsum[b];
    int i = b * 1024 + tid;
    if (i >= N) return;
    int rp = d_rowptr[i + 1] + off;
    d_rowptr[i + 1] = rp;
    d_cursor[i] = rp - d_deg[i];
    if (i == 0) d_rowptr[0] = 0;
}

// edges via cursor atomic; self loop takes guaranteed-last slot (no atomic)
__global__ void k_fill(const int* __restrict__ ei, int E, int N) {
    int i = blockIdx.x * blockDim.x + threadIdx.x;
    int T = E + N;
    if (i >= T) return;
    if (i < E) {
        int s = ei[i], dd = ei[E + i];
        int pos = atomicAdd(&d_cursor[dd], 1);
        d_col[pos] = s;
    } else {
        int n = i - E;
        d_col[d_rowptr[n + 1] - 1] = n;
    }
}

// ---------------- GAT aggregation (round-12; LAYER2 fuses mean-pool) ----------------
template <bool LAYER2>
__global__ void __launch_bounds__(128) k_agg(
    const float* __restrict__ bias, void* __restrict__ OUT,
    const int* __restrict__ batch, int N)
{
    __shared__ float4 s_e4[4][32];
    __shared__ int    s_src[4][32];
    __shared__ float  s_out[4][32];
    __shared__ int    s_b[4];

    int tid = threadIdx.x;
    int w = tid >> 5, lane = tid & 31;
    int n = blockIdx.x * 4 + w;
    bool valid = (n < N);
    if (!LAYER2 && !valid) return;
    int h = lane >> 3;

    if (valid) {
        int start = d_rowptr[n], end = d_rowptr[n + 1];
        float4 ad = ((const float4*)d_ADST)[n];

        float m = -INFINITY, den = 0.f;
        float4 acc = make_float4(0.f, 0.f, 0.f, 0.f);
        const float* se = (const float*)&s_e4[w][0];
        const int*   ss = &s_src[w][0];
        const uint2* XH8 = (const uint2*)d_XHh;

        for (int k0 = start; k0 < end; k0 += 32) {
            int len = min(32, end - k0);
            float4 e4 = make_float4(-INFINITY, -INFINITY, -INFINITY, -INFINITY);
            int s = 0;
            if (lane < len) {
                s = __ldg(&d_col[k0 + lane]);
                float4 as = __ldg(&((const float4*)d_ASRC)[s]);
                e4.x = as.x + ad.x; e4.x = e4.x > 0.f ? e4.x : 0.2f * e4.x;
                e4.y = as.y + ad.y; e4.y = e4.y > 0.f ? e4.y : 0.2f * e4.y;
                e4.z = as.z + ad.z; e4.z = e4.z > 0.f ? e4.z : 0.2f * e4.z;
                e4.w = as.w + ad.w; e4.w = e4.w > 0.f ? e4.w : 0.2f * e4.w;
            }
            s_src[w][lane] = s;
            s_e4[w][lane] = e4;

            float4 mx = e4;
#pragma unroll
            for (int o = 16; o >= 1; o >>= 1) {
                mx.x = fmaxf(mx.x, __shfl_xor_sync(0xffffffffu, mx.x, o));
                mx.y = fmaxf(mx.y, __shfl_xor_sync(0xffffffffu, mx.y, o));
                mx.z = fmaxf(mx.z, __shfl_xor_sync(0xffffffffu, mx.z, o));
                mx.w = fmaxf(mx.w, __shfl_xor_sync(0xffffffffu, mx.w, o));
            }
            float cmh = (h == 0) ? mx.x : (h == 1) ? mx.y : (h == 2) ? mx.z : mx.w;
            float cm = fmaxf(m, cmh);
            float scale = __expf(m - cm);
            acc.x *= scale; acc.y *= scale; acc.z *= scale; acc.w *= scale;
            den *= scale;

            __syncwarp();
#pragma unroll 4
            for (int j = 0; j < len; j++) {
                float p = __expf(se[j * 4 + h] - cm);
                den += p;
                uint2 r = __ldg(&XH8[ss[j] * 32 + lane]);
                float2 f0 = __half22float2(*(const __half2*)&r.x);
                float2 f1 = __half22float2(*(const __half2*)&r.y);
                acc.x = fmaf(p, f0.x, acc.x);
                acc.y = fmaf(p, f0.y, acc.y);
                acc.z = fmaf(p, f1.x, acc.z);
                acc.w = fmaf(p, f1.y, acc.w);
            }
            m = cm;
            __syncwarp();
        }

        float inv = 1.f / (den + 1e-16f);
        float4 val = make_float4(acc.x * inv, acc.y * inv, acc.z * inv, acc.w * inv);

        if (!LAYER2) {
            float4 b4 = ((const float4*)bias)[lane];
            val.x = fmaxf(val.x + b4.x, 0.f);
            val.y = fmaxf(val.y + b4.y, 0.f);
            val.z = fmaxf(val.z + b4.z, 0.f);
            val.w = fmaxf(val.w + b4.w, 0.f);
            __half2 h0 = __floats2half2_rn(val.x, val.y);
            __half2 h1 = __floats2half2_rn(val.z, val.w);
            uint2 p; p.x = *(uint32_t*)&h0; p.y = *(uint32_t*)&h1;
            ((uint2*)OUT)[n * 32 + lane] = p;     // fp16 H1
        } else {
#pragma unroll
            for (int o = 8; o <= 16; o <<= 1) {
                val.x += __shfl_xor_sync(0xffffffffu, val.x, o);
                val.y += __shfl_xor_sync(0xffffffffu, val.y, o);
                val.z += __shfl_xor_sync(0xffffffffu, val.z, o);
                val.w += __shfl_xor_sync(0xffffffffu, val.w, o);
            }
            if (lane < 8) {
                float4 b4 = ((const float4*)bias)[lane];
                s_out[w][lane * 4 + 0] = 0.25f * val.x + b4.x;
                s_out[w][lane * 4 + 1] = 0.25f * val.y + b4.y;
                s_out[w][lane * 4 + 2] = 0.25f * val.z + b4.z;
                s_out[w][lane * 4 + 3] = 0.25f * val.w + b4.w;
            }
            if (lane == 0) s_b[w] = batch[n];
        }
    } else if (LAYER2 && lane == 0) {
        s_b[w] = -1;
    }

    if (LAYER2) {
        __syncthreads();
        if (tid < 32) {
            float sum = 0.f;
            int curb = -1;
#pragma unroll
            for (int w2 = 0; w2 < 4; w2++) {
                int b = s_b[w2];
                if (b < 0) continue;
                if (b != curb) {
                    if (curb >= 0) atomicAdd(&d_gsum[curb * 32 + tid], sum);
                    curb = b; sum = 0.f;
                }
                sum += s_out[w2][tid];
            }
            if (curb >= 0) atomicAdd(&d_gsum[curb * 32 + tid], sum);
        }
    }
}

// ---------------- final MLP ----------------
__global__ void k_mlp(const int* __restrict__ batch, int N,
                      const float* __restrict__ stats,
                      const float* __restrict__ Wm1, const float* __restrict__ bm1,
                      const float* __restrict__ Wm2, const float* __restrict__ bm2,
                      float* __restrict__ out, int B)
{
    int g = threadIdx.x;
    if (g >= B) return;
    int lo0 = 0, hi0 = N;
    while (lo0 < hi0) { int mid = (lo0 + hi0) >> 1; if (batch[mid] < g) lo0 = mid + 1; else hi0 = mid; }
    int lo1 = lo0, hi1 = N;
    while (lo1 < hi1) { int mid = (lo1 + hi1) >> 1; if (batch[mid] < g + 1) lo1 = mid + 1; else hi1 = mid; }
    float cnt = (float)(lo1 - lo0);
    float inv = 1.f / fmaxf(cnt, 1.f);

    float v[47];
#pragma unroll
    for (int cc = 0; cc < 32; cc++) v[cc] = d_gsum[g * 32 + cc] * inv;
#pragma unroll
    for (int f = 0; f < 15; f++) v[32 + f] = stats[g * 15 + f];
    float o = bm2[0];
    for (int k = 0; k < 32; k++) {
        float hsum = bm1[k];
#pragma unroll
        for (int i = 0; i < 47; i++) hsum = fmaf(v[i], Wm1[i * 32 + k], hsum);
        o = fmaf(fmaxf(hsum, 0.f), Wm2[k], o);
    }
    out[g] = o;
}

// ---------------- launch ----------------
extern "C" void kernel_launch(void* const* d_in, const int* in_sizes, int n_in,
                              void* d_out, int out_size)
{
    const float* x     = (const float*)d_in[0];
    const int*   ei    = (const int*)d_in[1];
    const int*   batch = (const int*)d_in[2];
    const float* stats = (const float*)d_in[3];
    const float* W1    = (const float*)d_in[4];
    const float* as1   = (const float*)d_in[5];
    const float* ad1   = (const float*)d_in[6];
    const float* b1    = (const float*)d_in[7];
    const float* W2    = (const float*)d_in[8];
    const float* as2   = (const float*)d_in[9];
    const float* ad2   = (const float*)d_in[10];
    const float* b2    = (const float*)d_in[11];
    const float* Wm1   = (const float*)d_in[12];
    const float* bm1   = (const float*)d_in[13];
    const float* Wm2   = (const float*)d_in[14];
    const float* bm2   = (const float*)d_in[15];

    int N = in_sizes[0] / 128;
    int E = in_sizes[1] / 2;
    int B = in_sizes[3] / 15;

    __half *Wt1, *Wt2; __half2 *H1h;
    cudaGetSymbolAddress((void**)&Wt1, d_Wt1);
    cudaGetSymbolAddress((void**)&Wt2, d_Wt2);
    cudaGetSymbolAddress((void**)&H1h, d_H1h);

    // side stream + events (host objects; created once)
    static cudaStream_t s_side = nullptr;
    static cudaEvent_t  s_ev0 = nullptr, s_ev1 = nullptr;
    if (!s_side) {
        cudaStreamCreateWithFlags(&s_side, cudaStreamNonBlocking);
        cudaEventCreateWithFlags(&s_ev0, cudaEventDisableTiming);
        cudaEventCreateWithFlags(&s_ev1, cudaEventDisableTiming);
    }

    int numTiles   = (N + 127) / 128;
    int gemmBlocks = 296;                 // 2 CTAs/SM x 148 SMs: balanced persistent waves
    if (gemmBlocks > numTiles) gemmBlocks = numTiles;
    int edgeBlocks = (E + 255) / 256;
    int fillBlocks = (E + N + 255) / 256;
    int aggBlocks  = (N + 3) / 4;
    int scanBlocks = (N + 1023) / 1024;

    // fork: side stream handles graph init + CSR build (L2/atomic-bound, low occupancy)
    cudaEventRecord(s_ev0, 0);
    cudaStreamWaitEvent(s_side, s_ev0, 0);

    k_init_g<<<64, 256, 0, s_side>>>(N, B);
    k_deg  <<<edgeBlocks, 256, 0, s_side>>>(ei, E);
    k_scan1<<<scanBlocks, 1024, 0, s_side>>>(N);
    k_scan3<<<scanBlocks, 1024, 0, s_side>>>(N);
    k_fill <<<fillBlocks, 256, 0, s_side>>>(ei, E, N);
    cudaEventRecord(s_ev1, s_side);

    // main stream: weight prep + GEMM1 co-runs with CSR chain
    k_init_w<<<64, 256>>>(W1, W2);
    k_gemm_att<false><<<gemmBlocks, 256>>>(x, Wt1, as1, ad1, N, numTiles);

    cudaStreamWaitEvent(0, s_ev1, 0);   // join: agg needs CSR + GEMM1
    k_agg<false><<<aggBlocks, 128>>>(b1, H1h, batch, N);

    k_gemm_att<true><<<gemmBlocks, 256>>>(H1h, Wt2, as2, ad2, N, numTiles);
    k_agg<true><<<aggBlocks, 128>>>(b2, nullptr, batch, N);

    k_mlp<<<1, 128>>>(batch, N, stats, Wm1, bm1, Wm2, bm2, (float*)d_out, B);
}